// round 8
// baseline (speedup 1.0000x reference)
#include <cuda_runtime.h>
#include <cstddef>

// ---------------- problem constants ----------------
#define BB   64
#define TT   1024
#define II   128
#define HH   512
#define KK   640            // I + H

// ---------------- partitioning ----------------
#define GH   32             // hidden groups
#define GB   4              // batch groups
#define NCTA (GH*GB)        // 128 CTAs, one per SM, all resident
#define UH   16             // hidden units per CTA
#define UB   16             // batches per CTA
#define NTHR 256            // 16 u x 4 bq x 4 ks

#define WST  644            // smem row stride: 644 % 32 == 4 -> LDS.128 phase-friendly
#define HXST 644
#define REDST 20            // reduction row stride (16 data + 4 pad floats)
#define KQ   40             // ulonglong2 (4-float) chunks per k-quarter: 640/4/4

typedef unsigned long long ull;

// persistent state (no cudaMalloc allowed)
__device__ float    g_Hbuf[2][BB*HH];
__device__ unsigned g_bar[GB * 32];   // one counter per batch group, separate lines

// ---------------- packed fp32x2 helpers (Blackwell) ----------------
__device__ __forceinline__ ull ffma2(ull a, ull b, ull c) {
    ull d;
    asm("fma.rn.f32x2 %0, %1, %2, %3;" : "=l"(d) : "l"(a), "l"(b), "l"(c));
    return d;
}
__device__ __forceinline__ ull pack2(float lo, float hi) {
    ull d; asm("mov.b64 %0, {%1, %2};" : "=l"(d) : "f"(lo), "f"(hi)); return d;
}
__device__ __forceinline__ float red2(ull v) {
    return __uint_as_float((unsigned)v) + __uint_as_float((unsigned)(v >> 32));
}
__device__ __forceinline__ float sigm(float x) { return 1.0f / (1.0f + expf(-x)); }

__device__ __forceinline__ unsigned ld_acq(const unsigned* p) {
    unsigned v;
    asm volatile("ld.acquire.gpu.global.u32 %0, [%1];" : "=r"(v) : "l"(p) : "memory");
    return v;
}

__global__ void slstm_init_kernel() {
    if (threadIdx.x < GB) g_bar[threadIdx.x * 32] = 0u;
}

// ---------------- persistent sLSTM kernel ----------------
extern "C" __global__ void __launch_bounds__(NTHR, 1)
sLSTM_70772471103948_kernel(const float* __restrict__ x,     // [B,T,I]
                            const float* __restrict__ W_ih,  // [4H,I]
                            const float* __restrict__ W_hh,  // [4H,H]
                            const float* __restrict__ b_ih,  // [4H]
                            const float* __restrict__ b_hh,  // [4H]
                            const float* __restrict__ Wf,    // [H,H]
                            const float* __restrict__ bf,    // [H]
                            float* __restrict__ out,         // [B,T,H] | h[B,H] | c[B,H]
                            long long out_elems)
{
    extern __shared__ float smem[];
    float* Wsm = smem;                           // 64 rows x WST
    float* hx  = smem + 64 * WST;                // 16 batch rows x HXST ([x_t | h_t])
    float* red = hx + UB * HXST;                 // 256 rows x REDST (phase-1 partials)

    const int tid = threadIdx.x;
    const int u   = tid & 15;                    // local hidden unit
    const int q   = tid >> 4;                    // 0..15: owned local batch
    const int bq  = q >> 2;                      // phase-1 batch quad
    const int ks  = q & 3;                       // phase-1 k quarter (== owned slot)
    const int hg  = blockIdx.x & (GH - 1);
    const int bg  = blockIdx.x >> 5;
    const int j0  = hg * UH;
    const int b0  = bg * UB;
    const int j   = j0 + u;                      // global hidden index
    const int gb  = b0 + q;                      // global owned batch

    // ---- stage gate weights into SMEM once ----
    for (int idx = tid; idx < 64 * KK; idx += NTHR) {
        int r  = idx / KK;
        int k  = idx - r * KK;
        int gg = r >> 4, uu = r & 15;
        int grow = gg * HH + j0 + uu;            // gate order: i,f,g,o
        float w = (k < II) ? W_ih[grow * II + k] : W_hh[grow * HH + (k - II)];
        Wsm[r * WST + k] = w;
    }
    // ---- stage x_0 ; h_0 = 0 ----
    {
        const float4* xs = (const float4*)x;
        #pragma unroll
        for (int it = 0; it < (UB * II / 4) / NTHR; it++) {
            int idx = tid + it * NTHR;
            int b = idx >> 5, k4 = idx & 31;
            *(float4*)(hx + b * HXST + k4 * 4) =
                xs[((size_t)(b0 + b) * TT + 0) * (II / 4) + k4];
        }
        float4 z = make_float4(0.f, 0.f, 0.f, 0.f);
        #pragma unroll
        for (int it = 0; it < (UB * HH / 4) / NTHR; it++) {
            int idx = tid + it * NTHR;
            int b = idx >> 7, k4 = idx & 127;
            *(float4*)(hx + b * HXST + II + k4 * 4) = z;
        }
    }
    const float bias0 = b_ih[0 * HH + j] + b_hh[0 * HH + j];
    const float bias1 = b_ih[1 * HH + j] + b_hh[1 * HH + j];
    const float bias2 = b_ih[2 * HH + j] + b_hh[2 * HH + j];
    const float bias3 = b_ih[3 * HH + j] + b_hh[3 * HH + j];
    const float bfj = bf[j];

    __syncthreads();

    // phase-1 pointers: 4 gate-weight rows (this u, this k-quarter), 4 value rows (this bq)
    const ulonglong2* wP0 = (const ulonglong2*)(Wsm + (0 * 16 + u) * WST) + ks * KQ;
    const ulonglong2* wP1 = (const ulonglong2*)(Wsm + (1 * 16 + u) * WST) + ks * KQ;
    const ulonglong2* wP2 = (const ulonglong2*)(Wsm + (2 * 16 + u) * WST) + ks * KQ;
    const ulonglong2* wP3 = (const ulonglong2*)(Wsm + (3 * 16 + u) * WST) + ks * KQ;
    const ulonglong2* vP0 = (const ulonglong2*)(hx + (bq * 4 + 0) * HXST) + ks * KQ;
    const ulonglong2* vP1 = (const ulonglong2*)(hx + (bq * 4 + 1) * HXST) + ks * KQ;
    const ulonglong2* vP2 = (const ulonglong2*)(hx + (bq * 4 + 2) * HXST) + ks * KQ;
    const ulonglong2* vP3 = (const ulonglong2*)(hx + (bq * 4 + 3) * HXST) + ks * KQ;
    float* myred = red + (q * 16 + u) * REDST;
    const float4* wfrow = (const float4*)(Wf + (size_t)j * HH);
    const ulonglong2* hmine = (const ulonglong2*)(hx + q * HXST + II);
    unsigned* mybar = &g_bar[bg * 32];

    float cc = 0.f, hv_ = 0.f;                   // owned (j, gb) state

    #pragma unroll 1
    for (int t = 0; t < TT; t++) {
        // ===== phase 1: 4 gates x 4 batches over this thread's k-quarter =====
        ull a00 = 0, a01 = 0, a02 = 0, a03 = 0;
        ull a10 = 0, a11 = 0, a12 = 0, a13 = 0;
        ull a20 = 0, a21 = 0, a22 = 0, a23 = 0;
        ull a30 = 0, a31 = 0, a32 = 0, a33 = 0;
        #pragma unroll 2
        for (int kk = 0; kk < KQ; kk++) {
            ulonglong2 w0 = wP0[kk], w1 = wP1[kk], w2 = wP2[kk], w3 = wP3[kk];
            ulonglong2 v0 = vP0[kk], v1 = vP1[kk], v2 = vP2[kk], v3 = vP3[kk];
            a00 = ffma2(w0.x, v0.x, a00); a00 = ffma2(w0.y, v0.y, a00);
            a01 = ffma2(w0.x, v1.x, a01); a01 = ffma2(w0.y, v1.y, a01);
            a02 = ffma2(w0.x, v2.x, a02); a02 = ffma2(w0.y, v2.y, a02);
            a03 = ffma2(w0.x, v3.x, a03); a03 = ffma2(w0.y, v3.y, a03);
            a10 = ffma2(w1.x, v0.x, a10); a10 = ffma2(w1.y, v0.y, a10);
            a11 = ffma2(w1.x, v1.x, a11); a11 = ffma2(w1.y, v1.y, a11);
            a12 = ffma2(w1.x, v2.x, a12); a12 = ffma2(w1.y, v2.y, a12);
            a13 = ffma2(w1.x, v3.x, a13); a13 = ffma2(w1.y, v3.y, a13);
            a20 = ffma2(w2.x, v0.x, a20); a20 = ffma2(w2.y, v0.y, a20);
            a21 = ffma2(w2.x, v1.x, a21); a21 = ffma2(w2.y, v1.y, a21);
            a22 = ffma2(w2.x, v2.x, a22); a22 = ffma2(w2.y, v2.y, a22);
            a23 = ffma2(w2.x, v3.x, a23); a23 = ffma2(w2.y, v3.y, a23);
            a30 = ffma2(w3.x, v0.x, a30); a30 = ffma2(w3.y, v0.y, a30);
            a31 = ffma2(w3.x, v1.x, a31); a31 = ffma2(w3.y, v1.y, a31);
            a32 = ffma2(w3.x, v2.x, a32); a32 = ffma2(w3.y, v2.y, a32);
            a33 = ffma2(w3.x, v3.x, a33); a33 = ffma2(w3.y, v3.y, a33);
        }
        // publish fp32 partials: one float4 per gate (4 batches)
        ((float4*)myred)[0] = make_float4(red2(a00), red2(a01), red2(a02), red2(a03));
        ((float4*)myred)[1] = make_float4(red2(a10), red2(a11), red2(a12), red2(a13));
        ((float4*)myred)[2] = make_float4(red2(a20), red2(a21), red2(a22), red2(a23));
        ((float4*)myred)[3] = make_float4(red2(a30), red2(a31), red2(a32), red2(a33));
        __syncthreads();                          // S1

        // ===== gather 4 k-quarter partials for owned (u, gb); activation =====
        float g0, g1, g2, g3;
        {
            const float* rp = red + (bq * 4 * 16 + u) * REDST + ks;
            g0 = rp[0]; g1 = rp[4]; g2 = rp[8]; g3 = rp[12];
            #pragma unroll
            for (int kr = 1; kr < 4; kr++) {
                const float* r2 = rp + kr * 16 * REDST;
                g0 += r2[0]; g1 += r2[4]; g2 += r2[8]; g3 += r2[12];
            }
        }
        {
            float iv = sigm(g0 + bias0);
            float fv = sigm(g1 + bias1);
            float gv = tanhf(g2 + bias2);
            float ov = sigm(g3 + bias3);
            cc  = fv * cc + iv * gv;
            hv_ = ov * tanhf(cc);
        }
        const int p1 = (t + 1) & 1;
        out[((size_t)gb * TT + t) * HH + j] = hv_;
        __stcg(&g_Hbuf[p1][gb * HH + j], hv_);

        // prefetch x_{t+1} (independent of barrier; phase-1 reads finished at S1)
        if (t + 1 < TT) {
            const float4* xs = (const float4*)x;
            #pragma unroll
            for (int it = 0; it < (UB * II / 4) / NTHR; it++) {
                int idx = tid + it * NTHR;
                int b = idx >> 5, k4 = idx & 31;
                *(float4*)(hx + b * HXST + k4 * 4) =
                    xs[((size_t)(b0 + b) * TT + (t + 1)) * (II / 4) + k4];
            }
        }
        __syncthreads();                          // S2: all h stores issued CTA-wide

        // ===== per-batch-group grid barrier (32 CTAs) =====
        if (tid == 0) {
            __threadfence();                      // release h writes
            atomicAdd(mybar, 1u);
            const unsigned target = (unsigned)(t + 1) * GH;
            while (ld_acq(mybar) < target) { }
        }
        __syncthreads();                          // S3

        // ===== stage h_{t+1} into SMEM (vectorized) =====
        {
            const float4* hb = (const float4*)g_Hbuf[p1];
            #pragma unroll
            for (int it = 0; it < (UB * HH / 4) / NTHR; it++) {
                int idx = tid + it * NTHR;
                int b = idx >> 7, k4 = idx & 127;
                float4 v = __ldcg(&hb[(size_t)(b0 + b) * (HH / 4) + k4]);
                *(float4*)(hx + b * HXST + II + k4 * 4) = v;
            }
        }
        __syncthreads();                          // S4

        // ===== fe = exp(h_new @ Wf^T + bf); c *= fe  (owned batch, FULL k=512) =====
        {
            ull s0 = 0, s1 = 0;
            #pragma unroll 4
            for (int qk = 0; qk < HH / 4; qk++) {   // 128 iters x 4 floats = 512  (R7 bug: was HH/8)
                float4 w = __ldg(&wfrow[qk]);
                ulonglong2 hvv = hmine[qk];
                s0 = ffma2(pack2(w.x, w.y), hvv.x, s0);
                s1 = ffma2(pack2(w.z, w.w), hvv.y, s1);
            }
            cc *= expf(red2(s0) + red2(s1) + bfj);
        }
    }

    // ===== final h, c (tuple flatten: out | h | c) =====
    if (out_elems >= (long long)BB * TT * HH + 2LL * BB * HH) {
        float* hout = out + (size_t)BB * TT * HH;
        float* cout = hout + (size_t)BB * HH;
        hout[gb * HH + j] = hv_;
        cout[gb * HH + j] = cc;
    }
}

extern "C" void kernel_launch(void* const* d_in, const int* in_sizes, int n_in,
                              void* d_out, int out_size) {
    const float* x    = (const float*)d_in[0];
    const float* W_ih = (const float*)d_in[1];
    const float* W_hh = (const float*)d_in[2];
    const float* b_ih = (const float*)d_in[3];
    const float* b_hh = (const float*)d_in[4];
    const float* Wf   = (const float*)d_in[5];
    const float* bf   = (const float*)d_in[6];
    // d_in[7] = Wi, d_in[8] = bi: unused by the reference recurrence
    float* out = (float*)d_out;

    const size_t smem_bytes =
        (size_t)(64 * WST + UB * HXST + 256 * REDST) * sizeof(float); // 226,560 B
    cudaFuncSetAttribute(sLSTM_70772471103948_kernel,
                         cudaFuncAttributeMaxDynamicSharedMemorySize, (int)smem_bytes);

    slstm_init_kernel<<<1, 32>>>();
    sLSTM_70772471103948_kernel<<<NCTA, NTHR, smem_bytes>>>(
        x, W_ih, W_hh, b_ih, b_hh, Wf, bf, out, (long long)out_size);
}